// round 13
// baseline (speedup 1.0000x reference)
#include <cuda_runtime.h>

// Problem shapes (fixed by the dataset).
constexpr int Bb = 16;
constexpr int Kk = 128;
constexpr int Nn = 8192;
constexpr int Mm = Nn + Kk;   // 8320
constexpr int GX = 19;        // blocks per batch (19*448 = 8512 >= 8320)
constexpr int TT = 448;       // threads per block (14 warps)
constexpr int NW = TT / 32;   // 14 warps

// Output packing: tuple concatenated in return order, all float32.
constexpr size_t OFF_ROIS = 0;
constexpr size_t OFF_LAB  = (size_t)Bb * Mm * 5;
constexpr size_t OFF_TGT  = OFF_LAB + (size_t)Bb * Mm;
constexpr size_t OFF_IW   = OFF_TGT + (size_t)Bb * Mm * 4;
constexpr size_t OFF_OW   = OFF_IW  + (size_t)Bb * Mm * 4;

// Scratch (no allocations allowed -> __device__ globals).
__device__ int g_bcnt[Bb * GX];  // per-block fg counts (rewritten every launch)
__device__ int g_cnt[Bb];        // monotone ticket counters: never reset, so the
                                 // barrier is correct across graph replays; the
                                 // outputs never depend on the counter value.

// ---------------------------------------------------------------------------
// Single fused kernel, balanced single wave: 304 blocks = exactly 2/SM on
// 152 SMs (launch_bounds(448,2) guarantees co-residency -> spin barrier is
// deadlock-free).
// Phase A: per-roi IoU max/argmax over K gt boxes (lean division-free loop),
//          focal weights (original order), per-warp fg ballots.
// Handoff: block publishes its fg COUNT immediately (before weight stores,
//          overlapping them with other blocks' publishes), then spins on the
//          per-batch ticket barrier. Only 19 ints cross blocks — no bitmask.
// Phase B: dest = predecessor-block counts (warp shfl-reduce of 19 ints) +
//          in-block warp prefix (smem) + in-warp ballot prefix; scatter
//          rois/labels/targets with coords still live in registers.
// ---------------------------------------------------------------------------
__global__ __launch_bounds__(TT, 2)
void k_fused(const float* __restrict__ rois,
             const float* __restrict__ gt,
             float* __restrict__ out) {
    const int b = blockIdx.y;
    const int bx = blockIdx.x;
    const int t = threadIdx.x;
    const int lane = t & 31, wid = t >> 5;
    const int m = bx * TT + t;
    const bool valid = (m < Mm);
    const int mm = valid ? m : (Mm - 1);

    __shared__ float4 sc[Kk];                    // gx1, gy1, gx2+1 (-1e30 if zero-area), gy2+1
    __shared__ __align__(16) float ssar[Kk];     // gt area (reference expression)
    __shared__ float slab[Kk];                   // gt label
    __shared__ int   s_wc[NW];                   // per-warp fg counts

    const float* gtb = gt + (size_t)b * Kk * 5;

    // Hoisted roi loads: issue DRAM loads before the smem prologue so their
    // latency overlaps the gt tile fill.
    const float* rp = (mm < Nn) ? (rois + ((size_t)b * Nn + mm) * 5 + 1)
                                : (gtb + (size_t)(mm - Nn) * 5);
    const float x1 = rp[0], y1 = rp[1], x2 = rp[2], y2 = rp[3];

    if (t < Kk) {
        float gx1 = gtb[t * 5 + 0], gy1 = gtb[t * 5 + 1];
        float gx2 = gtb[t * 5 + 2], gy2 = gtb[t * 5 + 3];
        float w = gx2 - gx1 + 1.0f, h = gy2 - gy1 + 1.0f;
        bool zf = (w == 1.0f) && (h == 1.0f);
        sc[t] = make_float4(gx1, gy1, zf ? -1e30f : (gx2 + 1.0f), gy2 + 1.0f);
        ssar[t] = w * h;
        slab[t] = gtb[t * 5 + 4];
    }
    __syncthreads();

    const float aw = x2 - x1 + 1.0f;
    const float ah = y2 - y1 + 1.0f;
    const float aA = aw * ah;
    const float X2p = x2 + 1.0f, Y2p = y2 + 1.0f;

    float bI = 0.0f, bS = 1.0f;
    int arg = 0;

    #pragma unroll 2
    for (int kk = 0; kk < Kk; kk += 4) {
        const float4 sa4 = *(const float4*)&ssar[kk];
        const float sas[4] = {sa4.x, sa4.y, sa4.z, sa4.w};
        #pragma unroll
        for (int j = 0; j < 4; ++j) {
            const int k = kk + j;
            const float4 c = sc[k];
            float iw = fmaxf(fminf(X2p, c.z) - fmaxf(x1, c.x), 0.0f);
            float ih = fminf(Y2p, c.w) - fmaxf(y1, c.y);   // unclamped: ih<0 -> in_<=0 never wins
            float in_ = iw * ih;
            float S = aA + sas[j];
            bool p = in_ * bS > bI * S;
            bI = p ? in_ : bI;
            bS = p ? S : bS;
            arg = p ? k : arg;
        }
    }

    float mo; int a; bool fg;
    if ((aw == 1.0f) && (ah == 1.0f)) {        // zero-area roi (absent in data)
        mo = -1.0f; fg = false; a = 0;
    } else if (m >= Nn) {                      // appended gt: self-IoU == 1 exactly
        mo = 1.0f; fg = true; a = m - Nn;
    } else {
        mo = bI / (bS - bI);                   // one exact div, reference expression
        fg = (mo >= 0.5f);
        a = arg;
    }
    fg = fg && valid;
    const unsigned bal = __ballot_sync(0xffffffffu, fg);
    if (lane == 0) s_wc[wid] = __popc(bal);
    __syncthreads();                            // s_wc complete

    // Publish this block's fg count ASAP (before weight stores).
    if (t == 0) {
        int c = 0;
        #pragma unroll
        for (int w = 0; w < NW; ++w) c += s_wc[w];
        g_bcnt[b * GX + bx] = c;
        __threadfence();
        const int ticket = atomicAdd(&g_cnt[b], 1);
        const int target = (ticket / GX + 1) * GX;
        while (atomicAdd(&g_cnt[b], 0) < target) __nanosleep(64);
        __threadfence();
    }

    // Independent work overlapping other blocks' publishes: focal weights in
    // ORIGINAL roi order.
    if (valid) {
        const int idx = b * Mm + m;
        const float om = 1.0f - mo;
        const float w = fg ? om * om : 0.0f;
        const float ow = (w > 0.0f) ? 1.0f : 0.0f;
        ((float4*)(out + OFF_IW))[idx] = make_float4(w, w, w, w);
        ((float4*)(out + OFF_OW))[idx] = make_float4(ow, ow, ow, ow);
    }

    __syncthreads();                            // barrier released by t==0
    if (!valid) return;

    // ---- dest index from 19 block counts + in-block prefix (no gmem scan) ----
    int wc = (lane < NW) ? s_wc[lane] : 0;      // in-block per-warp counts
    int bc = (lane < GX) ? g_bcnt[b * GX + lane] : 0;
    // pack: low 16 = in-block warp prefix contrib, high 16 = predecessor-block contrib
    int pk = ((lane < wid) ? wc : 0) | (((lane < bx) ? bc : 0) << 16);
    int tt_ = bc;                               // total fg in batch
    #pragma unroll
    for (int o = 16; o > 0; o >>= 1) {
        pk  += __shfl_xor_sync(0xffffffffu, pk, o);
        tt_ += __shfl_xor_sync(0xffffffffu, tt_, o);
    }
    const int pre = (pk & 0xffff) + (pk >> 16) + __popc(bal & ((1u << lane) - 1u));
    const int d = fg ? pre : tt_ + (m - pre);

    // ---- scatter with live registers ----
    float* rb = out + OFF_ROIS + ((size_t)b * Mm + d) * 5;
    rb[0] = (float)b; rb[1] = x1; rb[2] = y1; rb[3] = x2; rb[4] = y2;

    float lab = 0.0f;
    float t0 = 0.0f, t1 = 0.0f, t2 = 0.0f, t3 = 0.0f;
    if (fg) {
        const float4 c = sc[a];                    // assigned gt, smem-resident
        lab = slab[a];                             // labels in {1..3}
        float ew = x2 - x1 + 1.0f, eh = y2 - y1 + 1.0f;
        float ecx = x1 + 0.5f * ew, ecy = y1 + 0.5f * eh;
        float gw = c.z - c.x, gh = c.w - c.y;      // (x2+1)-x1: <=1 ulp vs reference
        float gcx = c.x + 0.5f * gw, gcy = c.y + 0.5f * gh;
        t0 = ((gcx - ecx) / ew) / 0.1f;
        t1 = ((gcy - ecy) / eh) / 0.1f;
        t2 = logf(gw / ew) / 0.2f;
        t3 = logf(gh / eh) / 0.2f;
    }
    out[OFF_LAB + (size_t)b * Mm + d] = lab;
    ((float4*)(out + OFF_TGT))[(size_t)b * Mm + d] = make_float4(t0, t1, t2, t3);
}

extern "C" void kernel_launch(void* const* d_in, const int* in_sizes, int n_in,
                              void* d_out, int out_size) {
    const float* rois = (const float*)d_in[0];   // (B, N, 5)
    const float* gt   = (const float*)d_in[1];   // (B, K, 5)
    float* out = (float*)d_out;

    dim3 grid(GX, Bb);                           // 19 x 16 = 304 blocks = 2/SM exactly
    k_fused<<<grid, TT>>>(rois, gt, out);
}